// round 2
// baseline (speedup 1.0000x reference)
#include <cuda_runtime.h>

#define B_TOTAL 4096
#define V_TOTAL 1024
#define DD 64
#define TB 64
#define TV 64
#define LDX 66   // padded row stride (words) for xs

// Zero-initialized scratch. Min encoded as key = ~bits(value); value >= 0 so
// bit order == value order, max key == min value, and 0 is the identity for
// atomicMax (every real key > 0x80000000). Last block resets to 0 -> graph-safe.
__device__ unsigned int g_rowmin_key[B_TOTAL];   // min over v, per b
__device__ unsigned int g_colmin_key[V_TOTAL];   // min over b, per v
__device__ unsigned int g_arrive;

// d = a + b (b pre-negated); acc += |d|, all packed f32x2, one asm region so
// ptxas allocates the temp pair locally (no cross-boundary 64-bit copies).
__device__ __forceinline__ void l1acc(unsigned long long& acc,
                                      unsigned long long a,
                                      unsigned long long b) {
    asm("{\n\t"
        ".reg .b64 d;\n\t"
        "add.rn.f32x2 d, %1, %2;\n\t"
        "and.b64 d, d, 0x7FFFFFFF7FFFFFFF;\n\t"
        "add.rn.f32x2 %0, %0, d;\n\t"
        "}"
        : "+l"(acc) : "l"(a), "l"(b));
}

__global__ __launch_bounds__(128)
void dist_fused(const float* __restrict__ x, const float* __restrict__ p,
                float* __restrict__ out, int nblocks) {
    __shared__ float xs[TB][LDX];          // b-major, k contiguous
    __shared__ float ps2[DD / 2][TV][2];   // k-pair interleaved, negated
    __shared__ unsigned int col_s[TV];
    __shared__ float red[8];
    __shared__ bool is_last;

    const int tid = threadIdx.x;
    const int b0 = blockIdx.y * TB;
    const int v0 = blockIdx.x * TV;

    // ---- load x tile ----
    for (int i = tid; i < TB * (DD / 4); i += 128) {
        int r = i >> 4;
        int c = (i & 15) << 2;
        float4 v = *(const float4*)(x + (size_t)(b0 + r) * DD + c);
        xs[r][c]     = v.x;
        xs[r][c + 1] = v.y;
        xs[r][c + 2] = v.z;
        xs[r][c + 3] = v.w;
    }
    // ---- load p tile negated, k-pair interleaved ----
    for (int i = tid; i < TV * (DD / 4); i += 128) {
        int r = i >> 4;
        int c = (i & 15) << 2;
        float4 v = *(const float4*)(p + (size_t)(v0 + r) * DD + c);
        int kk = c >> 1;
        ps2[kk][r][0]     = -v.x;
        ps2[kk][r][1]     = -v.y;
        ps2[kk + 1][r][0] = -v.z;
        ps2[kk + 1][r][1] = -v.w;
    }
    if (tid < TV) col_s[tid] = 0u;   // key identity
    __syncthreads();

    const int tx = tid & 15;   // v = tx + 16*j  (bank-conflict-free LDS.64)
    const int ty = tid >> 4;   // b = ty*8 + i
    const int brow = ty * 8;

    unsigned long long acc[8][4];
#pragma unroll
    for (int i = 0; i < 8; i++)
#pragma unroll
        for (int j = 0; j < 4; j++) acc[i][j] = 0ull;

#pragma unroll 2
    for (int kk = 0; kk < DD / 2; kk++) {
        unsigned long long xr[8], pr[4];
#pragma unroll
        for (int i = 0; i < 8; i++)
            xr[i] = *(const unsigned long long*)&xs[brow + i][kk * 2];
#pragma unroll
        for (int j = 0; j < 4; j++)
            pr[j] = *(const unsigned long long*)&ps2[kk][tx + 16 * j][0];
#pragma unroll
        for (int i = 0; i < 8; i++)
#pragma unroll
            for (int j = 0; j < 4; j++)
                l1acc(acc[i][j], xr[i], pr[j]);
    }

    // ---- horizontal pair sum ----
    float dist[8][4];
#pragma unroll
    for (int i = 0; i < 8; i++)
#pragma unroll
        for (int j = 0; j < 4; j++) {
            unsigned long long a = acc[i][j];
            float lo = __uint_as_float((unsigned int)(a & 0xFFFFFFFFull));
            float hi = __uint_as_float((unsigned int)(a >> 32));
            dist[i][j] = lo + hi;
        }

    // ---- write distances (coalesced 64B segments) ----
#pragma unroll
    for (int i = 0; i < 8; i++) {
        size_t rowbase = (size_t)(b0 + brow + i) * V_TOTAL + v0;
#pragma unroll
        for (int j = 0; j < 4; j++)
            out[rowbase + tx + 16 * j] = dist[i][j];
    }

    // ---- row mins: butterfly over the 16 tx lanes, key-encoded atomicMax ----
#pragma unroll
    for (int i = 0; i < 8; i++) {
        float rm = fminf(fminf(dist[i][0], dist[i][1]), fminf(dist[i][2], dist[i][3]));
        rm = fminf(rm, __shfl_xor_sync(0xFFFFFFFFu, rm, 1));
        rm = fminf(rm, __shfl_xor_sync(0xFFFFFFFFu, rm, 2));
        rm = fminf(rm, __shfl_xor_sync(0xFFFFFFFFu, rm, 4));
        rm = fminf(rm, __shfl_xor_sync(0xFFFFFFFFu, rm, 8));
        if (tx == 0)
            atomicMax(&g_rowmin_key[b0 + brow + i], ~__float_as_uint(rm));
    }

    // ---- col mins: smem stage, then global key atomicMax ----
#pragma unroll
    for (int j = 0; j < 4; j++) {
        float cm = dist[0][j];
#pragma unroll
        for (int i = 1; i < 8; i++) cm = fminf(cm, dist[i][j]);
        atomicMax(&col_s[tx + 16 * j], ~__float_as_uint(cm));
    }
    __syncthreads();
    if (tid < TV)
        atomicMax(&g_colmin_key[v0 + tid], col_s[tid]);

    // ---- last-block finalize ----
    __threadfence();
    if (tid == 0)
        is_last = (atomicAdd(&g_arrive, 1u) == (unsigned)(nblocks - 1));
    __syncthreads();
    if (!is_last) return;

    // r1 = mean over v of colmin; r2 = mean over b of rowmin
    float s1 = 0.f, s2 = 0.f;
    for (int i = tid; i < V_TOTAL; i += 128)
        s1 += __uint_as_float(~__ldcg(&g_colmin_key[i]));
    for (int i = tid; i < B_TOTAL; i += 128)
        s2 += __uint_as_float(~__ldcg(&g_rowmin_key[i]));
#pragma unroll
    for (int o = 16; o > 0; o >>= 1) {
        s1 += __shfl_xor_sync(0xFFFFFFFFu, s1, o);
        s2 += __shfl_xor_sync(0xFFFFFFFFu, s2, o);
    }
    int wid = tid >> 5;
    if ((tid & 31) == 0) { red[wid] = s1; red[4 + wid] = s2; }
    __syncthreads();
    if (tid == 0) {
        float r1 = red[0] + red[1] + red[2] + red[3];
        float r2 = red[4] + red[5] + red[6] + red[7];
        out[(size_t)B_TOTAL * V_TOTAL]     = r1 / (float)V_TOTAL;
        out[(size_t)B_TOTAL * V_TOTAL + 1] = r2 / (float)B_TOTAL;
        g_arrive = 0u;   // restore state for graph replay
    }
    // reset key scratch to the zero identity for the next replay
    for (int i = tid; i < B_TOTAL; i += 128) g_rowmin_key[i] = 0u;
    for (int i = tid; i < V_TOTAL; i += 128) g_colmin_key[i] = 0u;
}

extern "C" void kernel_launch(void* const* d_in, const int* in_sizes, int n_in,
                              void* d_out, int out_size) {
    (void)in_sizes; (void)n_in; (void)out_size;
    const float* x = (const float*)d_in[0];
    const float* p = (const float*)d_in[1];
    float* out = (float*)d_out;

    dim3 grid(V_TOTAL / TV, B_TOTAL / TB);   // (16, 64) = 1024 blocks
    dist_fused<<<grid, 128>>>(x, p, out, V_TOTAL / TV * (B_TOTAL / TB));
}